// round 3
// baseline (speedup 1.0000x reference)
#include <cuda_runtime.h>
#include <cuda_bf16.h>
#include <math.h>

// Problem constants
#define T_TOK   32768          // B*S = 8*4096
#define DIM     512
#define HEADS   8
#define DH      64
#define SCALE_F 0.125f

// Scratch (static device globals; no runtime allocation)
__device__ float g_Wz[DIM * DIM];            // (Wq - Wk) * scale, row-major [512][512]
__device__ float g_O [T_TOK * DIM];          // softmax(z) * v, row-major [32768][512]

// ---------------------------------------------------------------------------
// K0: fold Wz = (W_qkv[:, 0:512] - W_qkv[:, 512:1024]) * SCALE
// ---------------------------------------------------------------------------
__global__ void prep_wz_kernel(const float* __restrict__ Wqkv) {
    int i = blockIdx.x * blockDim.x + threadIdx.x;   // 0 .. 512*512-1
    int r = i >> 9;
    int c = i & 511;
    g_Wz[i] = (Wqkv[r * 1536 + c] - Wqkv[r * 1536 + 512 + c]) * SCALE_F;
}

// ---------------------------------------------------------------------------
// K1: per head h: z = x@Wz[:,h] + bz, v = x@Wv[:,h] + bv,
//     O[:, h*64:(h+1)*64] = softmax(z over 64) * v
// Tile: 128 tokens x 64 cols (one head), two accumulator sets (z and v).
// 256 threads, 8x4 microtile each, KC=16.
// ---------------------------------------------------------------------------
__global__ __launch_bounds__(256) void zv_softmax_kernel(
    const float* __restrict__ x,
    const float* __restrict__ Wqkv,
    const float* __restrict__ bqkv)
{
    __shared__ __align__(16) float As [16][132];   // transposed: As[k][token]
    __shared__ __align__(16) float Bzs[16][68];
    __shared__ __align__(16) float Bvs[16][68];

    const int tid = threadIdx.x;
    const int ty  = tid >> 4;     // 0..15  (rows)
    const int tx  = tid & 15;     // 0..15  (cols)

    const int tokBase = blockIdx.x * 128;
    const int head    = blockIdx.y;
    const int colBase = head * DH;

    const float* xblk = x + (size_t)tokBase * DIM;
    const float* wv   = Wqkv + 1024 + colBase;     // v columns, row stride 1536

    float cz[8][4];
    float cv[8][4];
#pragma unroll
    for (int i = 0; i < 8; ++i)
#pragma unroll
        for (int j = 0; j < 4; ++j) { cz[i][j] = 0.f; cv[i][j] = 0.f; }

    for (int kt = 0; kt < DIM; kt += 16) {
        // ---- load A (128x16), store transposed ----
#pragma unroll
        for (int it = 0; it < 2; ++it) {
            int idx = it * 256 + tid;        // 0..511
            int t   = idx >> 2;              // token in tile
            int q   = idx & 3;               // k-group
            float4 a = *(const float4*)(xblk + (size_t)t * DIM + kt + q * 4);
            As[q * 4 + 0][t] = a.x;
            As[q * 4 + 1][t] = a.y;
            As[q * 4 + 2][t] = a.z;
            As[q * 4 + 3][t] = a.w;
        }
        // ---- load Bz (16x64) and Bv (16x64), one float4 each per thread ----
        {
            int kk = tid >> 4;               // 0..15
            int c4 = tid & 15;               // 0..15
            float4 bz = *(const float4*)(g_Wz + (size_t)(kt + kk) * DIM + colBase + c4 * 4);
            *(float4*)&Bzs[kk][c4 * 4] = bz;
            float4 bv = *(const float4*)(wv + (size_t)(kt + kk) * 1536 + c4 * 4);
            *(float4*)&Bvs[kk][c4 * 4] = bv;
        }
        __syncthreads();

#pragma unroll
        for (int kk = 0; kk < 16; ++kk) {
            float4 a0 = *(const float4*)&As[kk][ty * 8];
            float4 a1 = *(const float4*)&As[kk][ty * 8 + 4];
            float a[8] = {a0.x, a0.y, a0.z, a0.w, a1.x, a1.y, a1.z, a1.w};
            float4 bz4 = *(const float4*)&Bzs[kk][tx * 4];
            float4 bv4 = *(const float4*)&Bvs[kk][tx * 4];
            float bz[4] = {bz4.x, bz4.y, bz4.z, bz4.w};
            float bv[4] = {bv4.x, bv4.y, bv4.z, bv4.w};
#pragma unroll
            for (int i = 0; i < 8; ++i) {
#pragma unroll
                for (int j = 0; j < 4; ++j) {
                    cz[i][j] = fmaf(a[i], bz[j], cz[i][j]);
                    cv[i][j] = fmaf(a[i], bv[j], cv[i][j]);
                }
            }
        }
        __syncthreads();
    }

    // ---- epilogue: add biases, per-row (64-wide) softmax across 16 tx lanes ----
    float bzc[4], bvc[4];
#pragma unroll
    for (int j = 0; j < 4; ++j) {
        int c = colBase + tx * 4 + j;
        bzc[j] = (bqkv[c] - bqkv[512 + c]) * SCALE_F;
        bvc[j] = bqkv[1024 + c];
    }

#pragma unroll
    for (int i = 0; i < 8; ++i) {
        float z[4];
        float m = -INFINITY;
#pragma unroll
        for (int j = 0; j < 4; ++j) {
            z[j] = cz[i][j] + bzc[j];
            m = fmaxf(m, z[j]);
        }
        // row max across the 16 column lanes (xor <= 8 stays within the group)
#pragma unroll
        for (int o = 8; o >= 1; o >>= 1)
            m = fmaxf(m, __shfl_xor_sync(0xffffffffu, m, o));

        float e[4];
        float s = 0.f;
#pragma unroll
        for (int j = 0; j < 4; ++j) {
            e[j] = expf(z[j] - m);
            s += e[j];
        }
#pragma unroll
        for (int o = 8; o >= 1; o >>= 1)
            s += __shfl_xor_sync(0xffffffffu, s, o);

        float inv = 1.0f / s;
        float4 o4;
        o4.x = e[0] * inv * (cv[i][0] + bvc[0]);
        o4.y = e[1] * inv * (cv[i][1] + bvc[1]);
        o4.z = e[2] * inv * (cv[i][2] + bvc[2]);
        o4.w = e[3] * inv * (cv[i][3] + bvc[3]);

        int t = tokBase + ty * 8 + i;
        *(float4*)(g_O + (size_t)t * DIM + colBase + tx * 4) = o4;
    }
}

// ---------------------------------------------------------------------------
// K2: y = O @ W_proj + b_proj + x
// Tile: 128 tokens x 128 cols, 256 threads, 8x8 microtile, KC=16.
// ---------------------------------------------------------------------------
__global__ __launch_bounds__(256) void proj_add_kernel(
    const float* __restrict__ x,
    const float* __restrict__ Wp,
    const float* __restrict__ bp,
    float* __restrict__ y)
{
    __shared__ __align__(16) float As[16][132];   // transposed: As[k][token]
    __shared__ __align__(16) float Bs[16][132];   // Bs[k][col]

    const int tid = threadIdx.x;
    const int ty  = tid >> 4;
    const int tx  = tid & 15;

    const int tokBase = blockIdx.x * 128;
    const int colBase = blockIdx.y * 128;

    const float* oblk = g_O + (size_t)tokBase * DIM;

    float acc[8][8];
#pragma unroll
    for (int i = 0; i < 8; ++i)
#pragma unroll
        for (int j = 0; j < 8; ++j) acc[i][j] = 0.f;

    for (int kt = 0; kt < DIM; kt += 16) {
        // ---- A (128x16) transposed ----
#pragma unroll
        for (int it = 0; it < 2; ++it) {
            int idx = it * 256 + tid;
            int t   = idx >> 2;
            int q   = idx & 3;
            float4 a = *(const float4*)(oblk + (size_t)t * DIM + kt + q * 4);
            As[q * 4 + 0][t] = a.x;
            As[q * 4 + 1][t] = a.y;
            As[q * 4 + 2][t] = a.z;
            As[q * 4 + 3][t] = a.w;
        }
        // ---- B (16x128): two float4 per thread ----
#pragma unroll
        for (int it = 0; it < 2; ++it) {
            int idx = it * 256 + tid;        // 0..511
            int kk  = idx >> 5;              // 0..15
            int c4  = idx & 31;              // 0..31
            float4 b = *(const float4*)(Wp + (size_t)(kt + kk) * DIM + colBase + c4 * 4);
            *(float4*)&Bs[kk][c4 * 4] = b;
        }
        __syncthreads();

#pragma unroll
        for (int kk = 0; kk < 16; ++kk) {
            float4 a0 = *(const float4*)&As[kk][ty * 8];
            float4 a1 = *(const float4*)&As[kk][ty * 8 + 4];
            float a[8] = {a0.x, a0.y, a0.z, a0.w, a1.x, a1.y, a1.z, a1.w};
            float4 b0 = *(const float4*)&Bs[kk][tx * 8];
            float4 b1 = *(const float4*)&Bs[kk][tx * 8 + 4];
            float b[8] = {b0.x, b0.y, b0.z, b0.w, b1.x, b1.y, b1.z, b1.w};
#pragma unroll
            for (int i = 0; i < 8; ++i)
#pragma unroll
                for (int j = 0; j < 8; ++j)
                    acc[i][j] = fmaf(a[i], b[j], acc[i][j]);
        }
        __syncthreads();
    }

    // ---- epilogue: + b_proj + x ----
#pragma unroll
    for (int i = 0; i < 8; ++i) {
        int t = tokBase + ty * 8 + i;
        const float* xrow = x + (size_t)t * DIM + colBase + tx * 8;
        float*       yrow = y + (size_t)t * DIM + colBase + tx * 8;
        const float* brow = bp + colBase + tx * 8;
#pragma unroll
        for (int jj = 0; jj < 8; jj += 4) {
            float4 xv = *(const float4*)(xrow + jj);
            float4 bv = *(const float4*)(brow + jj);
            float4 ov;
            ov.x = acc[i][jj + 0] + bv.x + xv.x;
            ov.y = acc[i][jj + 1] + bv.y + xv.y;
            ov.z = acc[i][jj + 2] + bv.z + xv.z;
            ov.w = acc[i][jj + 3] + bv.w + xv.w;
            *(float4*)(yrow + jj) = ov;
        }
    }
}

// ---------------------------------------------------------------------------
// launch
// ---------------------------------------------------------------------------
extern "C" void kernel_launch(void* const* d_in, const int* in_sizes, int n_in,
                              void* d_out, int out_size)
{
    const float* x    = (const float*)d_in[0];   // [8,4096,512]
    const float* Wqkv = (const float*)d_in[1];   // [512,1536]
    const float* bqkv = (const float*)d_in[2];   // [1536]
    const float* Wp   = (const float*)d_in[3];   // [512,512]
    const float* bp   = (const float*)d_in[4];   // [512]
    float* y = (float*)d_out;                    // [8,4096,512]

    (void)in_sizes; (void)n_in; (void)out_size;

    // K0: fold (Wq - Wk) * scale
    prep_wz_kernel<<<(DIM * DIM) / 256, 256>>>(Wqkv);

    // K1: fused z/v GEMM + per-head softmax -> g_O
    dim3 g1(T_TOK / 128, HEADS);
    zv_softmax_kernel<<<g1, 256>>>(x, Wqkv, bqkv);

    // K2: projection GEMM + residual
    dim3 g2(T_TOK / 128, DIM / 128);
    proj_add_kernel<<<g2, 256>>>(x, Wp, bp, y);
}

// round 5
// speedup vs baseline: 4.6535x; 4.6535x over previous
#include <cuda_runtime.h>
#include <cuda_bf16.h>
#include <math.h>
#include <stdint.h>

#define T_TOK   32768
#define DIM     512
#define SCALE_F 0.125f

// smem tile geometry: rows of 32 bf16 (64B) padded to 40 bf16 (80B pitch).
// 80B pitch => the 8 ldmatrix row addresses land on distinct 16B banks groups.
#define PITCHB  80
#define ATILE   (128 * PITCHB)      // 10240 B per buffer (A and B identical)

// ------------------------- device scratch -------------------------
__device__ __nv_bfloat16 g_xb [(size_t)T_TOK * DIM];   // x in bf16
__device__ __nv_bfloat16 g_O  [(size_t)T_TOK * DIM];   // softmax*v in bf16
__device__ __nv_bfloat16 g_W2T[1024 * DIM];            // [n][k], n = h*128 + (z:0-63 | v:64-127)
__device__ __nv_bfloat16 g_WpT[DIM * DIM];             // W_proj^T [n][k]
__device__ float g_bz[DIM];
__device__ float g_bv[DIM];

// ------------------------- helpers -------------------------
__device__ __forceinline__ uint32_t smem_u32(const void* p) {
    uint32_t a;
    asm("{ .reg .u64 t; cvta.to.shared.u64 t, %1; cvt.u32.u64 %0, t; }" : "=r"(a) : "l"(p));
    return a;
}
__device__ __forceinline__ void cp16(uint32_t sa, const void* gp) {
    asm volatile("cp.async.cg.shared.global [%0], [%1], 16;" :: "r"(sa), "l"(gp));
}
__device__ __forceinline__ void ld4(uint32_t r[4], uint32_t addr) {
    asm volatile("ldmatrix.sync.aligned.m8n8.x4.shared.b16 {%0,%1,%2,%3}, [%4];"
                 : "=r"(r[0]), "=r"(r[1]), "=r"(r[2]), "=r"(r[3]) : "r"(addr));
}
__device__ __forceinline__ void mma16816(float c[4], const uint32_t a[4],
                                         uint32_t b0, uint32_t b1) {
    asm volatile("mma.sync.aligned.m16n8k16.row.col.f32.bf16.bf16.f32 "
                 "{%0,%1,%2,%3}, {%4,%5,%6,%7}, {%8,%9}, {%0,%1,%2,%3};"
                 : "+f"(c[0]), "+f"(c[1]), "+f"(c[2]), "+f"(c[3])
                 : "r"(a[0]), "r"(a[1]), "r"(a[2]), "r"(a[3]), "r"(b0), "r"(b1));
}

// ------------------------- prep kernels -------------------------
__global__ void prep_xb(const float* __restrict__ x) {
    size_t i = (size_t)blockIdx.x * blockDim.x + threadIdx.x;   // 4 floats each
    float4 v = *(const float4*)(x + i * 4);
    __nv_bfloat162 h0 = __floats2bfloat162_rn(v.x, v.y);
    __nv_bfloat162 h1 = __floats2bfloat162_rn(v.z, v.w);
    *(__nv_bfloat162*)(g_xb + i * 4)     = h0;
    *(__nv_bfloat162*)(g_xb + i * 4 + 2) = h1;
}
__global__ void prep_w2t(const float* __restrict__ Wqkv, const float* __restrict__ bqkv) {
    int i = blockIdx.x * blockDim.x + threadIdx.x;   // 0..1024*512-1
    int n = i >> 9, k = i & 511;
    int h = n >> 7, r = n & 127;
    float v;
    if (r < 64) {
        int c = h * 64 + r;
        v = (Wqkv[k * 1536 + c] - Wqkv[k * 1536 + 512 + c]) * SCALE_F;
    } else {
        int c = h * 64 + (r - 64);
        v = Wqkv[k * 1536 + 1024 + c];
    }
    g_W2T[n * 512 + k] = __float2bfloat16_rn(v);
    if (i < 512) {
        g_bz[i] = (bqkv[i] - bqkv[512 + i]) * SCALE_F;
        g_bv[i] = bqkv[1024 + i];
    }
}
__global__ void prep_wpt(const float* __restrict__ Wp) {
    int i = blockIdx.x * blockDim.x + threadIdx.x;   // 0..512*512-1
    int n = i >> 9, k = i & 511;
    g_WpT[n * 512 + k] = __float2bfloat16_rn(Wp[k * 512 + n]);
}

// ------------------------- shared mainloop -------------------------
// smem: A buffers [0, 2*ATILE), B buffers [2*ATILE, 4*ATILE)  = 40960 B
__device__ __forceinline__ void load_tiles(const __nv_bfloat16* __restrict__ Ag,
                                           const __nv_bfloat16* __restrict__ Bg,
                                           uint32_t sA, uint32_t sB, int kt, int tid) {
#pragma unroll
    for (int it = 0; it < 2; ++it) {
        int idx = it * 256 + tid;
        int row = idx >> 2, ch = idx & 3;
        size_t go = (size_t)row * 512 + kt * 32 + ch * 8;
        uint32_t so = (uint32_t)(row * PITCHB + ch * 16);
        cp16(sA + so, Ag + go);
        cp16(sB + so, Bg + go);
    }
}

__device__ __forceinline__ void run_mainloop(const __nv_bfloat16* __restrict__ Ag,
                                             const __nv_bfloat16* __restrict__ Bg,
                                             uint32_t sbase, int tid,
                                             float c[4][4][4]) {
#pragma unroll
    for (int i = 0; i < 4; ++i)
#pragma unroll
        for (int j = 0; j < 4; ++j)
#pragma unroll
            for (int q = 0; q < 4; ++q) c[i][j][q] = 0.f;

    const int l  = tid & 31;
    const int wm = (tid >> 5) >> 2;      // 0..1
    const int wn = (tid >> 5) & 3;       // 0..3
    // ldmatrix lane address offsets (within a buffer)
    const uint32_t aOff = (uint32_t)((wm * 64 + (l & 15)) * PITCHB + (l >> 4) * 16);
    const uint32_t bOff = (uint32_t)((wn * 32 + (l & 7) + ((l >> 4) & 1) * 8) * PITCHB
                                     + ((l >> 3) & 1) * 16);
    const uint32_t sA = sbase;
    const uint32_t sB = sbase + 2 * ATILE;

    load_tiles(Ag, Bg, sA, sB, 0, tid);
    asm volatile("cp.async.commit_group;" ::: "memory");

    for (int kt = 0; kt < 16; ++kt) {
        if (kt < 15) {
            load_tiles(Ag, Bg, sA + ((kt + 1) & 1) * ATILE, sB + ((kt + 1) & 1) * ATILE,
                       kt + 1, tid);
            asm volatile("cp.async.commit_group;" ::: "memory");
            asm volatile("cp.async.wait_group 1;" ::: "memory");
        } else {
            asm volatile("cp.async.wait_group 0;" ::: "memory");
        }
        __syncthreads();

        const uint32_t aB = sA + (kt & 1) * ATILE + aOff;
        const uint32_t bB = sB + (kt & 1) * ATILE + bOff;
#pragma unroll
        for (int ks = 0; ks < 2; ++ks) {
            uint32_t a[4][4];
#pragma unroll
            for (int mm = 0; mm < 4; ++mm) ld4(a[mm], aB + mm * 16 * PITCHB + ks * 32);
            uint32_t b[2][4];
#pragma unroll
            for (int pr = 0; pr < 2; ++pr) ld4(b[pr], bB + pr * 16 * PITCHB + ks * 32);
#pragma unroll
            for (int mm = 0; mm < 4; ++mm)
#pragma unroll
                for (int mn = 0; mn < 4; ++mn)
                    mma16816(c[mm][mn], a[mm], b[mn >> 1][(mn & 1) * 2],
                             b[mn >> 1][(mn & 1) * 2 + 1]);
        }
        __syncthreads();
    }
}

// ------------------------- GEMM1: zv + softmax -> g_O -------------------------
__global__ __launch_bounds__(256, 2) void gemm1_kernel() {
    __shared__ __align__(16) unsigned char sm[40960];
    const int tid = threadIdx.x;
    float c[4][4][4];

    const __nv_bfloat16* Ag = g_xb  + (size_t)blockIdx.x * 128 * DIM;
    const __nv_bfloat16* Bg = g_W2T + (size_t)blockIdx.y * 128 * DIM;
    run_mainloop(Ag, Bg, smem_u32(sm), tid, c);

    const int l  = tid & 31;
    const int wm = (tid >> 5) >> 2;
    const int wn = (tid >> 5) & 3;
    const int head = blockIdx.y;

    float* Psm = (float*)sm;               // [128][68] exp values (z half)
    float* Zs  = (float*)(sm + 34816);     // [2][128]  per-row partial sums

    if (wn < 2) {
        float bz2[4][2];
#pragma unroll
        for (int mn = 0; mn < 4; ++mn) {
            int cb = head * 64 + wn * 32 + mn * 8 + 2 * (l & 3);
            bz2[mn][0] = g_bz[cb];
            bz2[mn][1] = g_bz[cb + 1];
        }
#pragma unroll
        for (int mm = 0; mm < 4; ++mm)
#pragma unroll
            for (int rh = 0; rh < 2; ++rh) {
                int r = wm * 64 + mm * 16 + rh * 8 + (l >> 2);
                float part = 0.f;
#pragma unroll
                for (int mn = 0; mn < 4; ++mn) {
                    int cb = wn * 32 + mn * 8 + 2 * (l & 3);
                    float e0 = __expf(c[mm][mn][rh * 2 + 0] + bz2[mn][0]);
                    float e1 = __expf(c[mm][mn][rh * 2 + 1] + bz2[mn][1]);
                    part += e0 + e1;
                    float2 st = make_float2(e0, e1);
                    *(float2*)(Psm + r * 68 + cb) = st;
                }
                part += __shfl_xor_sync(0xffffffffu, part, 1);
                part += __shfl_xor_sync(0xffffffffu, part, 2);
                if ((l & 3) == 0) Zs[wn * 128 + r] = part;
            }
    }
    __syncthreads();
    if (wn >= 2) {
        float bv2[4][2];
#pragma unroll
        for (int mn = 0; mn < 4; ++mn) {
            int cb = head * 64 + (wn - 2) * 32 + mn * 8 + 2 * (l & 3);
            bv2[mn][0] = g_bv[cb];
            bv2[mn][1] = g_bv[cb + 1];
        }
#pragma unroll
        for (int mm = 0; mm < 4; ++mm)
#pragma unroll
            for (int rh = 0; rh < 2; ++rh) {
                int r = wm * 64 + mm * 16 + rh * 8 + (l >> 2);
                float inv = 1.0f / (Zs[r] + Zs[128 + r]);
                size_t grow = (size_t)blockIdx.x * 128 + r;
                __nv_bfloat16* op = g_O + grow * DIM + head * 64;
#pragma unroll
                for (int mn = 0; mn < 4; ++mn) {
                    int vc = (wn - 2) * 32 + mn * 8 + 2 * (l & 3);
                    float p0 = Psm[r * 68 + vc];
                    float p1 = Psm[r * 68 + vc + 1];
                    float o0 = p0 * inv * (c[mm][mn][rh * 2 + 0] + bv2[mn][0]);
                    float o1 = p1 * inv * (c[mm][mn][rh * 2 + 1] + bv2[mn][1]);
                    *(__nv_bfloat162*)(op + vc) = __floats2bfloat162_rn(o0, o1);
                }
            }
    }
}

// ------------------------- GEMM2: y = O @ Wp + bp + x -------------------------
__global__ __launch_bounds__(256, 2) void gemm2_kernel(const float* __restrict__ x,
                                                       const float* __restrict__ bp,
                                                       float* __restrict__ y) {
    __shared__ __align__(16) unsigned char sm[40960];
    const int tid = threadIdx.x;
    float c[4][4][4];

    const __nv_bfloat16* Ag = g_O   + (size_t)blockIdx.x * 128 * DIM;
    const __nv_bfloat16* Bg = g_WpT + (size_t)blockIdx.y * 128 * DIM;
    run_mainloop(Ag, Bg, smem_u32(sm), tid, c);

    const int l  = tid & 31;
    const int wm = (tid >> 5) >> 2;
    const int wn = (tid >> 5) & 3;
    const int cb0 = blockIdx.y * 128 + wn * 32;

    float2 bp2[4];
#pragma unroll
    for (int mn = 0; mn < 4; ++mn)
        bp2[mn] = *(const float2*)(bp + cb0 + mn * 8 + 2 * (l & 3));

#pragma unroll
    for (int mm = 0; mm < 4; ++mm)
#pragma unroll
        for (int rh = 0; rh < 2; ++rh) {
            int r = wm * 64 + mm * 16 + rh * 8 + (l >> 2);
            size_t grow = (size_t)blockIdx.x * 128 + r;
#pragma unroll
            for (int mn = 0; mn < 4; ++mn) {
                int col = cb0 + mn * 8 + 2 * (l & 3);
                float2 xv = *(const float2*)(x + grow * DIM + col);
                float2 o;
                o.x = c[mm][mn][rh * 2 + 0] + bp2[mn].x + xv.x;
                o.y = c[mm][mn][rh * 2 + 1] + bp2[mn].y + xv.y;
                *(float2*)(y + grow * DIM + col) = o;
            }
        }
}

// ------------------------- launch -------------------------
extern "C" void kernel_launch(void* const* d_in, const int* in_sizes, int n_in,
                              void* d_out, int out_size)
{
    const float* x    = (const float*)d_in[0];
    const float* Wqkv = (const float*)d_in[1];
    const float* bqkv = (const float*)d_in[2];
    const float* Wp   = (const float*)d_in[3];
    const float* bp   = (const float*)d_in[4];
    float* y = (float*)d_out;
    (void)in_sizes; (void)n_in; (void)out_size;

    prep_xb <<<(T_TOK * DIM / 4) / 256, 256>>>(x);
    prep_w2t<<<(1024 * DIM) / 256, 256>>>(Wqkv, bqkv);
    prep_wpt<<<(DIM * DIM) / 256, 256>>>(Wp);

    dim3 g1(T_TOK / 128, 8);    // 256 x 8  (N tile = one head's [z|v])
    gemm1_kernel<<<g1, 256>>>();

    dim3 g2(T_TOK / 128, 4);    // 256 x 4
    gemm2_kernel<<<g2, 256>>>(x, bp, y);
}

// round 6
// speedup vs baseline: 5.2192x; 1.1216x over previous
#include <cuda_runtime.h>
#include <cuda_bf16.h>
#include <math.h>
#include <stdint.h>

#define T_TOK   32768
#define DIM     512
#define SCALE_F 0.125f

// smem tile geometry: rows of 32 bf16 (64B) padded to 80B pitch (conflict-free ldmatrix)
#define PITCHB  80
#define ATILE   (128 * PITCHB)            // 10240 B (A: 128 rows)
#define BTILE   (256 * PITCHB)            // 20480 B (B: 256 rows)
#define STAGE   (ATILE + BTILE)           // 30720 B
#define NSTG    3
#define SMEM_BYTES (NSTG * STAGE)         // 92160 B

// ------------------------- device scratch -------------------------
__device__ __nv_bfloat16 g_xb [(size_t)T_TOK * DIM];   // x in bf16
__device__ __nv_bfloat16 g_O  [(size_t)T_TOK * DIM];   // softmax*v in bf16
__device__ __nv_bfloat16 g_W2T[1024 * DIM];            // [n][k], n = h*128 + (z:0-63 | v:64-127)
__device__ __nv_bfloat16 g_WpT[DIM * DIM];             // W_proj^T [n][k]
__device__ float g_bz[DIM];
__device__ float g_bv[DIM];

// ------------------------- helpers -------------------------
__device__ __forceinline__ uint32_t smem_u32(const void* p) {
    uint32_t a;
    asm("{ .reg .u64 t; cvta.to.shared.u64 t, %1; cvt.u32.u64 %0, t; }" : "=r"(a) : "l"(p));
    return a;
}
__device__ __forceinline__ void cp16(uint32_t sa, const void* gp) {
    asm volatile("cp.async.cg.shared.global [%0], [%1], 16;" :: "r"(sa), "l"(gp));
}
__device__ __forceinline__ void ld4(uint32_t r[4], uint32_t addr) {
    asm volatile("ldmatrix.sync.aligned.m8n8.x4.shared.b16 {%0,%1,%2,%3}, [%4];"
                 : "=r"(r[0]), "=r"(r[1]), "=r"(r[2]), "=r"(r[3]) : "r"(addr));
}
__device__ __forceinline__ void mma16816(float c[4], const uint32_t a[4],
                                         uint32_t b0, uint32_t b1) {
    asm volatile("mma.sync.aligned.m16n8k16.row.col.f32.bf16.bf16.f32 "
                 "{%0,%1,%2,%3}, {%4,%5,%6,%7}, {%8,%9}, {%0,%1,%2,%3};"
                 : "+f"(c[0]), "+f"(c[1]), "+f"(c[2]), "+f"(c[3])
                 : "r"(a[0]), "r"(a[1]), "r"(a[2]), "r"(a[3]), "r"(b0), "r"(b1));
}

// ------------------------- prep kernels -------------------------
__global__ void prep_xb(const float* __restrict__ x) {
    size_t i = (size_t)blockIdx.x * blockDim.x + threadIdx.x;
    float4 v = *(const float4*)(x + i * 4);
    *(__nv_bfloat162*)(g_xb + i * 4)     = __floats2bfloat162_rn(v.x, v.y);
    *(__nv_bfloat162*)(g_xb + i * 4 + 2) = __floats2bfloat162_rn(v.z, v.w);
}
__global__ void prep_w2t(const float* __restrict__ Wqkv, const float* __restrict__ bqkv) {
    int i = blockIdx.x * blockDim.x + threadIdx.x;   // 0..1024*512-1
    int n = i >> 9, k = i & 511;
    int h = n >> 7, r = n & 127;
    float v;
    if (r < 64) {
        int c = h * 64 + r;
        v = (Wqkv[k * 1536 + c] - Wqkv[k * 1536 + 512 + c]) * SCALE_F;
    } else {
        int c = h * 64 + (r - 64);
        v = Wqkv[k * 1536 + 1024 + c];
    }
    g_W2T[n * 512 + k] = __float2bfloat16_rn(v);
    if (i < 512) {
        g_bz[i] = (bqkv[i] - bqkv[512 + i]) * SCALE_F;
        g_bv[i] = bqkv[1024 + i];
    }
}
__global__ void prep_wpt(const float* __restrict__ Wp) {
    int i = blockIdx.x * blockDim.x + threadIdx.x;
    int n = i >> 9, k = i & 511;
    g_WpT[n * 512 + k] = __float2bfloat16_rn(Wp[k * 512 + n]);
}

// ------------------------- mainloop (128 x 256 tile, 512 thr, 3-stage) -------------------------
__device__ __forceinline__ void load_tiles(const __nv_bfloat16* __restrict__ Ag,
                                           const __nv_bfloat16* __restrict__ Bg,
                                           uint32_t stg, int kt, int tid) {
    if (kt < 16) {
        {   // A: 128 rows x 4 chunks = 512
            int row = tid >> 2, ch = tid & 3;
            cp16(stg + (uint32_t)(row * PITCHB + ch * 16),
                 Ag + (size_t)row * DIM + kt * 32 + ch * 8);
        }
#pragma unroll
        for (int it = 0; it < 2; ++it) {   // B: 256 rows x 4 chunks = 1024
            int idx = it * 512 + tid;
            int row = idx >> 2, ch = idx & 3;
            cp16(stg + ATILE + (uint32_t)(row * PITCHB + ch * 16),
                 Bg + (size_t)row * DIM + kt * 32 + ch * 8);
        }
    }
    asm volatile("cp.async.commit_group;" ::: "memory");
}

__device__ __forceinline__ void run_mainloop(const __nv_bfloat16* __restrict__ Ag,
                                             const __nv_bfloat16* __restrict__ Bg,
                                             uint32_t sbase, int tid,
                                             float c[4][4][4]) {
#pragma unroll
    for (int i = 0; i < 4; ++i)
#pragma unroll
        for (int j = 0; j < 4; ++j)
#pragma unroll
            for (int q = 0; q < 4; ++q) c[i][j][q] = 0.f;

    const int l  = tid & 31;
    const int w  = tid >> 5;       // 0..15
    const int wm = w >> 3;         // 0..1
    const int wn = w & 7;          // 0..7
    const uint32_t aOff = (uint32_t)((wm * 64 + (l & 15)) * PITCHB + (l >> 4) * 16);
    const uint32_t bOff = (uint32_t)(ATILE + (wn * 32 + (l & 7) + ((l >> 4) & 1) * 8) * PITCHB
                                     + ((l >> 3) & 1) * 16);

    load_tiles(Ag, Bg, sbase, 0, tid);
    load_tiles(Ag, Bg, sbase + STAGE, 1, tid);

    for (int kt = 0; kt < 16; ++kt) {
        asm volatile("cp.async.wait_group 1;" ::: "memory");
        __syncthreads();

        const uint32_t stg = sbase + (kt % NSTG) * STAGE;
        const uint32_t aB = stg + aOff;
        const uint32_t bB = stg + bOff;
#pragma unroll
        for (int ks = 0; ks < 2; ++ks) {
            uint32_t a[4][4];
#pragma unroll
            for (int mm = 0; mm < 4; ++mm) ld4(a[mm], aB + mm * 16 * PITCHB + ks * 32);
            uint32_t b[2][4];
#pragma unroll
            for (int pr = 0; pr < 2; ++pr) ld4(b[pr], bB + pr * 16 * PITCHB + ks * 32);
#pragma unroll
            for (int mm = 0; mm < 4; ++mm)
#pragma unroll
                for (int mn = 0; mn < 4; ++mn)
                    mma16816(c[mm][mn], a[mm], b[mn >> 1][(mn & 1) * 2],
                             b[mn >> 1][(mn & 1) * 2 + 1]);
        }
        load_tiles(Ag, Bg, sbase + ((kt + 2) % NSTG) * STAGE, kt + 2, tid);
    }
    asm volatile("cp.async.wait_group 0;" ::: "memory");
    __syncthreads();   // smem about to be reused by epilogue
}

// ------------------------- GEMM1: zv + softmax -> g_O -------------------------
__global__ __launch_bounds__(512, 1) void gemm1_kernel() {
    extern __shared__ __align__(16) unsigned char sm[];
    const int tid = threadIdx.x;
    float c[4][4][4];

    const __nv_bfloat16* Ag = g_xb  + (size_t)blockIdx.x * 128 * DIM;
    const __nv_bfloat16* Bg = g_W2T + (size_t)blockIdx.y * 256 * DIM;
    run_mainloop(Ag, Bg, smem_u32(sm), tid, c);

    const int l  = tid & 31;
    const int w  = tid >> 5;
    const int wm = w >> 3;
    const int wn = w & 7;
    const int h_l  = wn >> 2;                 // local head (0/1)
    const int half = wn & 1;                  // 32-col half within z or v
    const bool isZ = ((wn >> 1) & 1) == 0;
    const int head = blockIdx.y * 2 + h_l;

    float* Psm = (float*)sm;                  // [128][132] exp values (2 heads x 64 + pad)
    float* Zs  = (float*)(sm + 128 * 132 * 4); // [2 heads][2 halves][128]

    if (isZ) {
        float bz2[4][2];
#pragma unroll
        for (int mn = 0; mn < 4; ++mn) {
            int cb = head * 64 + half * 32 + mn * 8 + 2 * (l & 3);
            bz2[mn][0] = g_bz[cb];
            bz2[mn][1] = g_bz[cb + 1];
        }
#pragma unroll
        for (int mm = 0; mm < 4; ++mm)
#pragma unroll
            for (int rh = 0; rh < 2; ++rh) {
                int r = wm * 64 + mm * 16 + rh * 8 + (l >> 2);
                float part = 0.f;
#pragma unroll
                for (int mn = 0; mn < 4; ++mn) {
                    int cb = h_l * 64 + half * 32 + mn * 8 + 2 * (l & 3);
                    float e0 = __expf(c[mm][mn][rh * 2 + 0] + bz2[mn][0]);
                    float e1 = __expf(c[mm][mn][rh * 2 + 1] + bz2[mn][1]);
                    part += e0 + e1;
                    *(float2*)(Psm + r * 132 + cb) = make_float2(e0, e1);
                }
                part += __shfl_xor_sync(0xffffffffu, part, 1);
                part += __shfl_xor_sync(0xffffffffu, part, 2);
                if ((l & 3) == 0) Zs[(h_l * 2 + half) * 128 + r] = part;
            }
    }
    __syncthreads();
    if (!isZ) {
        float bv2[4][2];
#pragma unroll
        for (int mn = 0; mn < 4; ++mn) {
            int cb = head * 64 + half * 32 + mn * 8 + 2 * (l & 3);
            bv2[mn][0] = g_bv[cb];
            bv2[mn][1] = g_bv[cb + 1];
        }
#pragma unroll
        for (int mm = 0; mm < 4; ++mm)
#pragma unroll
            for (int rh = 0; rh < 2; ++rh) {
                int r = wm * 64 + mm * 16 + rh * 8 + (l >> 2);
                float inv = 1.0f / (Zs[(h_l * 2 + 0) * 128 + r] + Zs[(h_l * 2 + 1) * 128 + r]);
                size_t grow = (size_t)blockIdx.x * 128 + r;
                __nv_bfloat16* op = g_O + grow * DIM + head * 64;
#pragma unroll
                for (int mn = 0; mn < 4; ++mn) {
                    int vc = half * 32 + mn * 8 + 2 * (l & 3);
                    float p0 = Psm[r * 132 + h_l * 64 + vc];
                    float p1 = Psm[r * 132 + h_l * 64 + vc + 1];
                    float o0 = p0 * inv * (c[mm][mn][rh * 2 + 0] + bv2[mn][0]);
                    float o1 = p1 * inv * (c[mm][mn][rh * 2 + 1] + bv2[mn][1]);
                    *(__nv_bfloat162*)(op + vc) = __floats2bfloat162_rn(o0, o1);
                }
            }
    }
}

// ------------------------- GEMM2: y = O @ Wp + bp + x -------------------------
__global__ __launch_bounds__(512, 1) void gemm2_kernel(const float* __restrict__ x,
                                                       const float* __restrict__ bp,
                                                       float* __restrict__ y) {
    extern __shared__ __align__(16) unsigned char sm[];
    const int tid = threadIdx.x;
    float c[4][4][4];

    const __nv_bfloat16* Ag = g_O   + (size_t)blockIdx.x * 128 * DIM;
    const __nv_bfloat16* Bg = g_WpT + (size_t)blockIdx.y * 256 * DIM;
    run_mainloop(Ag, Bg, smem_u32(sm), tid, c);

    const int l  = tid & 31;
    const int w  = tid >> 5;
    const int wm = w >> 3;
    const int wn = w & 7;
    const int cb0 = blockIdx.y * 256 + wn * 32;

    float2 bp2[4];
#pragma unroll
    for (int mn = 0; mn < 4; ++mn)
        bp2[mn] = *(const float2*)(bp + cb0 + mn * 8 + 2 * (l & 3));

#pragma unroll
    for (int mm = 0; mm < 4; ++mm)
#pragma unroll
        for (int rh = 0; rh < 2; ++rh) {
            int r = wm * 64 + mm * 16 + rh * 8 + (l >> 2);
            size_t grow = (size_t)blockIdx.x * 128 + r;
#pragma unroll
            for (int mn = 0; mn < 4; ++mn) {
                int col = cb0 + mn * 8 + 2 * (l & 3);
                float2 xv = *(const float2*)(x + grow * DIM + col);
                float2 o;
                o.x = c[mm][mn][rh * 2 + 0] + bp2[mn].x + xv.x;
                o.y = c[mm][mn][rh * 2 + 1] + bp2[mn].y + xv.y;
                *(float2*)(y + grow * DIM + col) = o;
            }
        }
}

// ------------------------- launch -------------------------
extern "C" void kernel_launch(void* const* d_in, const int* in_sizes, int n_in,
                              void* d_out, int out_size)
{
    const float* x    = (const float*)d_in[0];
    const float* Wqkv = (const float*)d_in[1];
    const float* bqkv = (const float*)d_in[2];
    const float* Wp   = (const float*)d_in[3];
    const float* bp   = (const float*)d_in[4];
    float* y = (float*)d_out;
    (void)in_sizes; (void)n_in; (void)out_size;

    cudaFuncSetAttribute(gemm1_kernel, cudaFuncAttributeMaxDynamicSharedMemorySize, SMEM_BYTES);
    cudaFuncSetAttribute(gemm2_kernel, cudaFuncAttributeMaxDynamicSharedMemorySize, SMEM_BYTES);

    prep_xb <<<(T_TOK * DIM / 4) / 256, 256>>>(x);
    prep_w2t<<<(1024 * DIM) / 256, 256>>>(Wqkv, bqkv);
    prep_wpt<<<(DIM * DIM) / 256, 256>>>(Wp);

    dim3 g1(T_TOK / 128, 4);    // 256 x 4 (two heads per CTA)
    gemm1_kernel<<<g1, 512, SMEM_BYTES>>>();

    dim3 g2(T_TOK / 128, 2);    // 256 x 2
    gemm2_kernel<<<g2, 512, SMEM_BYTES>>>(x, bp, y);
}

// round 7
// speedup vs baseline: 5.3375x; 1.0227x over previous
#include <cuda_runtime.h>
#include <cuda_bf16.h>
#include <math.h>
#include <stdint.h>

#define T_TOK   32768
#define DIM     512
#define SCALE_F 0.125f

// smem tile geometry: rows of 32 bf16 (64B) padded to 80B pitch (conflict-free ldmatrix)
#define PITCHB  80
#define ATILE   (128 * PITCHB)            // 10240 B (A: 128 rows)
#define STAGE   (2 * ATILE)               // A + B = 20480 B
#define NSTG    4
#define SMEM_BYTES (NSTG * STAGE)         // 81920 B per CTA (2 CTAs/SM = 160 KB)

// ------------------------- device scratch -------------------------
__device__ __nv_bfloat16 g_xb [(size_t)T_TOK * DIM];   // x in bf16
__device__ __nv_bfloat16 g_O  [(size_t)T_TOK * DIM];   // softmax*v in bf16
__device__ __nv_bfloat16 g_W2T[1024 * DIM];            // [n][k], n = h*128 + (z:0-63 | v:64-127)
__device__ __nv_bfloat16 g_WpT[DIM * DIM];             // W_proj^T [n][k]
__device__ float g_bz[DIM];
__device__ float g_bv[DIM];

// ------------------------- helpers -------------------------
__device__ __forceinline__ uint32_t smem_u32(const void* p) {
    uint32_t a;
    asm("{ .reg .u64 t; cvta.to.shared.u64 t, %1; cvt.u32.u64 %0, t; }" : "=r"(a) : "l"(p));
    return a;
}
__device__ __forceinline__ void cp16(uint32_t sa, const void* gp) {
    asm volatile("cp.async.cg.shared.global [%0], [%1], 16;" :: "r"(sa), "l"(gp));
}
__device__ __forceinline__ void ld4(uint32_t r[4], uint32_t addr) {
    asm volatile("ldmatrix.sync.aligned.m8n8.x4.shared.b16 {%0,%1,%2,%3}, [%4];"
                 : "=r"(r[0]), "=r"(r[1]), "=r"(r[2]), "=r"(r[3]) : "r"(addr));
}
__device__ __forceinline__ void mma16816(float c[4], const uint32_t a[4],
                                         uint32_t b0, uint32_t b1) {
    asm volatile("mma.sync.aligned.m16n8k16.row.col.f32.bf16.bf16.f32 "
                 "{%0,%1,%2,%3}, {%4,%5,%6,%7}, {%8,%9}, {%0,%1,%2,%3};"
                 : "+f"(c[0]), "+f"(c[1]), "+f"(c[2]), "+f"(c[3])
                 : "r"(a[0]), "r"(a[1]), "r"(a[2]), "r"(a[3]), "r"(b0), "r"(b1));
}

// ------------------------- prep kernels -------------------------
__global__ void prep_xb(const float* __restrict__ x) {
    size_t i = (size_t)blockIdx.x * blockDim.x + threadIdx.x;
    float4 v = *(const float4*)(x + i * 4);
    *(__nv_bfloat162*)(g_xb + i * 4)     = __floats2bfloat162_rn(v.x, v.y);
    *(__nv_bfloat162*)(g_xb + i * 4 + 2) = __floats2bfloat162_rn(v.z, v.w);
}
__global__ void prep_w2t(const float* __restrict__ Wqkv, const float* __restrict__ bqkv) {
    int i = blockIdx.x * blockDim.x + threadIdx.x;   // 0..1024*512-1
    int n = i >> 9, k = i & 511;
    int h = n >> 7, r = n & 127;
    float v;
    if (r < 64) {
        int c = h * 64 + r;
        v = (Wqkv[k * 1536 + c] - Wqkv[k * 1536 + 512 + c]) * SCALE_F;
    } else {
        int c = h * 64 + (r - 64);
        v = Wqkv[k * 1536 + 1024 + c];
    }
    g_W2T[n * 512 + k] = __float2bfloat16_rn(v);
    if (i < 512) {
        g_bz[i] = (bqkv[i] - bqkv[512 + i]) * SCALE_F;
        g_bv[i] = bqkv[1024 + i];
    }
}
__global__ void prep_wpt(const float* __restrict__ Wp) {
    int i = blockIdx.x * blockDim.x + threadIdx.x;
    int n = i >> 9, k = i & 511;
    g_WpT[n * 512 + k] = __float2bfloat16_rn(Wp[k * 512 + n]);
}

// ------------------------- mainloop (128x128 tile, 256 thr, 4-stage) -------------------------
__device__ __forceinline__ void load_stage(const __nv_bfloat16* __restrict__ Ag,
                                           const __nv_bfloat16* __restrict__ Bg,
                                           uint32_t stg, int kt, int tid) {
    if (kt < 16) {
#pragma unroll
        for (int it = 0; it < 2; ++it) {
            int idx = it * 256 + tid;
            int row = idx >> 2, ch = idx & 3;
            uint32_t so = (uint32_t)(row * PITCHB + ch * 16);
            size_t go = (size_t)row * DIM + kt * 32 + ch * 8;
            cp16(stg + so, Ag + go);
            cp16(stg + ATILE + so, Bg + go);
        }
    }
    asm volatile("cp.async.commit_group;" ::: "memory");
}

__device__ __forceinline__ void ld_frags(uint32_t stg, int ks, uint32_t aOff, uint32_t bOff,
                                         uint32_t a[4][4], uint32_t b[2][4]) {
#pragma unroll
    for (int mm = 0; mm < 4; ++mm) ld4(a[mm], stg + aOff + mm * 16 * PITCHB + ks * 32);
#pragma unroll
    for (int pr = 0; pr < 2; ++pr) ld4(b[pr], stg + bOff + pr * 16 * PITCHB + ks * 32);
}

__device__ __forceinline__ void mma_all(float c[4][4][4], uint32_t a[4][4], uint32_t b[2][4]) {
#pragma unroll
    for (int mm = 0; mm < 4; ++mm)
#pragma unroll
        for (int mn = 0; mn < 4; ++mn)
            mma16816(c[mm][mn], a[mm], b[mn >> 1][(mn & 1) * 2], b[mn >> 1][(mn & 1) * 2 + 1]);
}

__device__ __forceinline__ void run_mainloop(const __nv_bfloat16* __restrict__ Ag,
                                             const __nv_bfloat16* __restrict__ Bg,
                                             uint32_t sbase, int tid,
                                             float c[4][4][4]) {
#pragma unroll
    for (int i = 0; i < 4; ++i)
#pragma unroll
        for (int j = 0; j < 4; ++j)
#pragma unroll
            for (int q = 0; q < 4; ++q) c[i][j][q] = 0.f;

    const int l  = tid & 31;
    const int w  = tid >> 5;       // 0..7
    const int wm = w >> 2;         // 0..1
    const int wn = w & 3;          // 0..3
    const uint32_t aOff = (uint32_t)((wm * 64 + (l & 15)) * PITCHB + (l >> 4) * 16);
    const uint32_t bOff = (uint32_t)(ATILE + (wn * 32 + (l & 7) + ((l >> 4) & 1) * 8) * PITCHB
                                     + ((l >> 3) & 1) * 16);

    load_stage(Ag, Bg, sbase + 0 * STAGE, 0, tid);
    load_stage(Ag, Bg, sbase + 1 * STAGE, 1, tid);
    load_stage(Ag, Bg, sbase + 2 * STAGE, 2, tid);
    asm volatile("cp.async.wait_group 1;" ::: "memory");   // stages 0,1 ready
    __syncthreads();

    uint32_t A0[4][4], B0[2][4], A1[4][4], B1[2][4];
    ld_frags(sbase, 0, aOff, bOff, A0, B0);

    for (int kt = 0; kt < 16; ++kt) {
        load_stage(Ag, Bg, sbase + ((kt + 3) & 3) * STAGE, kt + 3, tid);
        // ks = 0: prefetch ks=1 fragments, then MMA on ks=0
        ld_frags(sbase + (kt & 3) * STAGE, 1, aOff, bOff, A1, B1);
        mma_all(c, A0, B0);
        // ks = 1: prefetch next-kt ks=0 fragments (stage kt+1 guaranteed ready)
        ld_frags(sbase + ((kt + 1) & 3) * STAGE, 0, aOff, bOff, A0, B0);
        mma_all(c, A1, B1);

        asm volatile("cp.async.wait_group 1;" ::: "memory");
        __syncthreads();
    }
    asm volatile("cp.async.wait_group 0;" ::: "memory");
    __syncthreads();   // smem about to be reused by epilogue
}

// ------------------------- GEMM1: zv + softmax -> g_O -------------------------
// blockIdx.x = head (0..7) [fast dim -> A-tile L2 reuse], blockIdx.y = m-tile
__global__ __launch_bounds__(256, 2) void gemm1_kernel() {
    extern __shared__ __align__(16) unsigned char sm[];
    const int tid = threadIdx.x;
    float c[4][4][4];

    const __nv_bfloat16* Ag = g_xb  + (size_t)blockIdx.y * 128 * DIM;
    const __nv_bfloat16* Bg = g_W2T + (size_t)blockIdx.x * 128 * DIM;
    run_mainloop(Ag, Bg, smem_u32(sm), tid, c);

    const int l  = tid & 31;
    const int w  = tid >> 5;
    const int wm = w >> 2;
    const int wn = w & 3;
    const int head = blockIdx.x;

    float* Psm = (float*)sm;               // [128][68] exp values
    float* Zs  = (float*)(sm + 34816);     // [2][128] per-row partial sums

    if (wn < 2) {
        float bz2[4][2];
#pragma unroll
        for (int mn = 0; mn < 4; ++mn) {
            int cb = head * 64 + wn * 32 + mn * 8 + 2 * (l & 3);
            bz2[mn][0] = g_bz[cb];
            bz2[mn][1] = g_bz[cb + 1];
        }
#pragma unroll
        for (int mm = 0; mm < 4; ++mm)
#pragma unroll
            for (int rh = 0; rh < 2; ++rh) {
                int r = wm * 64 + mm * 16 + rh * 8 + (l >> 2);
                float part = 0.f;
#pragma unroll
                for (int mn = 0; mn < 4; ++mn) {
                    int cb = wn * 32 + mn * 8 + 2 * (l & 3);
                    float e0 = __expf(c[mm][mn][rh * 2 + 0] + bz2[mn][0]);
                    float e1 = __expf(c[mm][mn][rh * 2 + 1] + bz2[mn][1]);
                    part += e0 + e1;
                    *(float2*)(Psm + r * 68 + cb) = make_float2(e0, e1);
                }
                part += __shfl_xor_sync(0xffffffffu, part, 1);
                part += __shfl_xor_sync(0xffffffffu, part, 2);
                if ((l & 3) == 0) Zs[wn * 128 + r] = part;
            }
    }
    __syncthreads();
    if (wn >= 2) {
        float bv2[4][2];
#pragma unroll
        for (int mn = 0; mn < 4; ++mn) {
            int cb = head * 64 + (wn - 2) * 32 + mn * 8 + 2 * (l & 3);
            bv2[mn][0] = g_bv[cb];
            bv2[mn][1] = g_bv[cb + 1];
        }
#pragma unroll
        for (int mm = 0; mm < 4; ++mm)
#pragma unroll
            for (int rh = 0; rh < 2; ++rh) {
                int r = wm * 64 + mm * 16 + rh * 8 + (l >> 2);
                float inv = 1.0f / (Zs[r] + Zs[128 + r]);
                size_t grow = (size_t)blockIdx.y * 128 + r;
                __nv_bfloat16* op = g_O + grow * DIM + head * 64;
#pragma unroll
                for (int mn = 0; mn < 4; ++mn) {
                    int vc = (wn - 2) * 32 + mn * 8 + 2 * (l & 3);
                    float p0 = Psm[r * 68 + vc];
                    float p1 = Psm[r * 68 + vc + 1];
                    float o0 = p0 * inv * (c[mm][mn][rh * 2 + 0] + bv2[mn][0]);
                    float o1 = p1 * inv * (c[mm][mn][rh * 2 + 1] + bv2[mn][1]);
                    *(__nv_bfloat162*)(op + vc) = __floats2bfloat162_rn(o0, o1);
                }
            }
    }
}

// ------------------------- GEMM2: y = O @ Wp + bp + x -------------------------
// blockIdx.x = n-tile (0..3), blockIdx.y = m-tile
__global__ __launch_bounds__(256, 2) void gemm2_kernel(const float* __restrict__ x,
                                                       const float* __restrict__ bp,
                                                       float* __restrict__ y) {
    extern __shared__ __align__(16) unsigned char sm[];
    const int tid = threadIdx.x;
    float c[4][4][4];

    const __nv_bfloat16* Ag = g_O   + (size_t)blockIdx.y * 128 * DIM;
    const __nv_bfloat16* Bg = g_WpT + (size_t)blockIdx.x * 128 * DIM;
    run_mainloop(Ag, Bg, smem_u32(sm), tid, c);

    const int l  = tid & 31;
    const int w  = tid >> 5;
    const int wm = w >> 2;
    const int wn = w & 3;
    const int cb0 = blockIdx.x * 128 + wn * 32;

    float2 bp2[4];
#pragma unroll
    for (int mn = 0; mn < 4; ++mn)
        bp2[mn] = *(const float2*)(bp + cb0 + mn * 8 + 2 * (l & 3));

#pragma unroll
    for (int mm = 0; mm < 4; ++mm)
#pragma unroll
        for (int rh = 0; rh < 2; ++rh) {
            int r = wm * 64 + mm * 16 + rh * 8 + (l >> 2);
            size_t grow = (size_t)blockIdx.y * 128 + r;
#pragma unroll
            for (int mn = 0; mn < 4; ++mn) {
                int col = cb0 + mn * 8 + 2 * (l & 3);
                float2 xv = *(const float2*)(x + grow * DIM + col);
                float2 o;
                o.x = c[mm][mn][rh * 2 + 0] + bp2[mn].x + xv.x;
                o.y = c[mm][mn][rh * 2 + 1] + bp2[mn].y + xv.y;
                *(float2*)(y + grow * DIM + col) = o;
            }
        }
}

// ------------------------- launch -------------------------
extern "C" void kernel_launch(void* const* d_in, const int* in_sizes, int n_in,
                              void* d_out, int out_size)
{
    const float* x    = (const float*)d_in[0];
    const float* Wqkv = (const float*)d_in[1];
    const float* bqkv = (const float*)d_in[2];
    const float* Wp   = (const float*)d_in[3];
    const float* bp   = (const float*)d_in[4];
    float* y = (float*)d_out;
    (void)in_sizes; (void)n_in; (void)out_size;

    cudaFuncSetAttribute(gemm1_kernel, cudaFuncAttributeMaxDynamicSharedMemorySize, SMEM_BYTES);
    cudaFuncSetAttribute(gemm2_kernel, cudaFuncAttributeMaxDynamicSharedMemorySize, SMEM_BYTES);

    prep_xb <<<(T_TOK * DIM / 4) / 256, 256>>>(x);
    prep_w2t<<<(1024 * DIM) / 256, 256>>>(Wqkv, bqkv);
    prep_wpt<<<(DIM * DIM) / 256, 256>>>(Wp);

    dim3 g1(8, T_TOK / 128);    // head fast, m-tile slow
    gemm1_kernel<<<g1, 256, SMEM_BYTES>>>();

    dim3 g2(4, T_TOK / 128);
    gemm2_kernel<<<g2, 256, SMEM_BYTES>>>(x, bp, y);
}

// round 8
// speedup vs baseline: 5.3613x; 1.0045x over previous
#include <cuda_runtime.h>
#include <cuda_bf16.h>
#include <math.h>
#include <stdint.h>

#define T_TOK   32768
#define DIM     512
#define SCALE_F 0.125f

// smem tile geometry: rows of 32 bf16 (64B) padded to 80B pitch (conflict-free ldmatrix)
#define PITCHB  80
#define ATILE   (128 * PITCHB)            // 10240 B (A: 128 rows)
#define STAGE   (2 * ATILE)               // A + B = 20480 B
#define NSTG    4
#define SMEM_BYTES (NSTG * STAGE)         // 81920 B per CTA (2 CTAs/SM = 160 KB)

// ------------------------- device scratch -------------------------
__device__ __nv_bfloat16 g_xb [(size_t)T_TOK * DIM];   // x in bf16
__device__ __nv_bfloat16 g_O  [(size_t)T_TOK * DIM];   // softmax*v in bf16
__device__ __nv_bfloat16 g_W2T[1024 * DIM];            // [n][k], n = h*128 + (z:0-63 | v:64-127)
__device__ __nv_bfloat16 g_WpT[DIM * DIM];             // W_proj^T [n][k]
__device__ float g_bz[DIM];
__device__ float g_bv[DIM];

// ------------------------- helpers -------------------------
__device__ __forceinline__ uint32_t smem_u32(const void* p) {
    uint32_t a;
    asm("{ .reg .u64 t; cvta.to.shared.u64 t, %1; cvt.u32.u64 %0, t; }" : "=r"(a) : "l"(p));
    return a;
}
__device__ __forceinline__ void cp16(uint32_t sa, const void* gp) {
    asm volatile("cp.async.cg.shared.global [%0], [%1], 16;" :: "r"(sa), "l"(gp));
}
__device__ __forceinline__ void ld4(uint32_t r[4], uint32_t addr) {
    asm volatile("ldmatrix.sync.aligned.m8n8.x4.shared.b16 {%0,%1,%2,%3}, [%4];"
                 : "=r"(r[0]), "=r"(r[1]), "=r"(r[2]), "=r"(r[3]) : "r"(addr));
}
__device__ __forceinline__ void mma16816(float c[4], const uint32_t a[4],
                                         uint32_t b0, uint32_t b1) {
    asm volatile("mma.sync.aligned.m16n8k16.row.col.f32.bf16.bf16.f32 "
                 "{%0,%1,%2,%3}, {%4,%5,%6,%7}, {%8,%9}, {%0,%1,%2,%3};"
                 : "+f"(c[0]), "+f"(c[1]), "+f"(c[2]), "+f"(c[3])
                 : "r"(a[0]), "r"(a[1]), "r"(a[2]), "r"(a[3]), "r"(b0), "r"(b1));
}

// ------------------------- prep kernels -------------------------
__global__ void prep_xb(const float* __restrict__ x) {
    size_t i = (size_t)blockIdx.x * blockDim.x + threadIdx.x;
    float4 v = *(const float4*)(x + i * 4);
    *(__nv_bfloat162*)(g_xb + i * 4)     = __floats2bfloat162_rn(v.x, v.y);
    *(__nv_bfloat162*)(g_xb + i * 4 + 2) = __floats2bfloat162_rn(v.z, v.w);
}
__global__ void prep_w2t(const float* __restrict__ Wqkv, const float* __restrict__ bqkv) {
    int i = blockIdx.x * blockDim.x + threadIdx.x;   // 0..1024*512-1
    int n = i >> 9, k = i & 511;
    int h = n >> 7, r = n & 127;
    float v;
    if (r < 64) {
        int c = h * 64 + r;
        v = (Wqkv[k * 1536 + c] - Wqkv[k * 1536 + 512 + c]) * SCALE_F;
    } else {
        int c = h * 64 + (r - 64);
        v = Wqkv[k * 1536 + 1024 + c];
    }
    g_W2T[n * 512 + k] = __float2bfloat16_rn(v);
    if (i < 512) {
        g_bz[i] = (bqkv[i] - bqkv[512 + i]) * SCALE_F;
        g_bv[i] = bqkv[1024 + i];
    }
}
__global__ void prep_wpt(const float* __restrict__ Wp) {
    int i = blockIdx.x * blockDim.x + threadIdx.x;
    int n = i >> 9, k = i & 511;
    g_WpT[n * 512 + k] = __float2bfloat16_rn(Wp[k * 512 + n]);
}

// ------------------------- mainloop (128x128 tile, 256 thr, 4-stage) -------------------------
__device__ __forceinline__ void load_stage(const __nv_bfloat16* __restrict__ Ag,
                                           const __nv_bfloat16* __restrict__ Bg,
                                           uint32_t stg, int kt, int tid) {
    if (kt < 16) {
#pragma unroll
        for (int it = 0; it < 2; ++it) {
            int idx = it * 256 + tid;
            int row = idx >> 2, ch = idx & 3;
            uint32_t so = (uint32_t)(row * PITCHB + ch * 16);
            size_t go = (size_t)row * DIM + kt * 32 + ch * 8;
            cp16(stg + so, Ag + go);
            cp16(stg + ATILE + so, Bg + go);
        }
    }
    asm volatile("cp.async.commit_group;" ::: "memory");
}

__device__ __forceinline__ void ld_frags(uint32_t stg, int ks, uint32_t aOff, uint32_t bOff,
                                         uint32_t a[4][4], uint32_t b[2][4]) {
#pragma unroll
    for (int mm = 0; mm < 4; ++mm) ld4(a[mm], stg + aOff + mm * 16 * PITCHB + ks * 32);
#pragma unroll
    for (int pr = 0; pr < 2; ++pr) ld4(b[pr], stg + bOff + pr * 16 * PITCHB + ks * 32);
}

__device__ __forceinline__ void mma_all(float c[4][4][4], uint32_t a[4][4], uint32_t b[2][4]) {
#pragma unroll
    for (int mm = 0; mm < 4; ++mm)
#pragma unroll
        for (int mn = 0; mn < 4; ++mn)
            mma16816(c[mm][mn], a[mm], b[mn >> 1][(mn & 1) * 2], b[mn >> 1][(mn & 1) * 2 + 1]);
}

__device__ __forceinline__ void run_mainloop(const __nv_bfloat16* __restrict__ Ag,
                                             const __nv_bfloat16* __restrict__ Bg,
                                             uint32_t sbase, int tid,
                                             float c[4][4][4]) {
#pragma unroll
    for (int i = 0; i < 4; ++i)
#pragma unroll
        for (int j = 0; j < 4; ++j)
#pragma unroll
            for (int q = 0; q < 4; ++q) c[i][j][q] = 0.f;

    const int l  = tid & 31;
    const int w  = tid >> 5;       // 0..7
    const int wm = w >> 2;         // 0..1
    const int wn = w & 3;          // 0..3
    const uint32_t aOff = (uint32_t)((wm * 64 + (l & 15)) * PITCHB + (l >> 4) * 16);
    const uint32_t bOff = (uint32_t)(ATILE + (wn * 32 + (l & 7) + ((l >> 4) & 1) * 8) * PITCHB
                                     + ((l >> 3) & 1) * 16);

    load_stage(Ag, Bg, sbase + 0 * STAGE, 0, tid);
    load_stage(Ag, Bg, sbase + 1 * STAGE, 1, tid);
    load_stage(Ag, Bg, sbase + 2 * STAGE, 2, tid);
    asm volatile("cp.async.wait_group 1;" ::: "memory");   // stages 0,1 ready
    __syncthreads();

    uint32_t A0[4][4], B0[2][4], A1[4][4], B1[2][4];
    ld_frags(sbase, 0, aOff, bOff, A0, B0);

    for (int kt = 0; kt < 16; ++kt) {
        load_stage(Ag, Bg, sbase + ((kt + 3) & 3) * STAGE, kt + 3, tid);
        // ks = 0: prefetch ks=1 fragments, then MMA on ks=0
        ld_frags(sbase + (kt & 3) * STAGE, 1, aOff, bOff, A1, B1);
        mma_all(c, A0, B0);
        // ks = 1: prefetch next-kt ks=0 fragments (stage kt+1 guaranteed ready)
        ld_frags(sbase + ((kt + 1) & 3) * STAGE, 0, aOff, bOff, A0, B0);
        mma_all(c, A1, B1);

        asm volatile("cp.async.wait_group 1;" ::: "memory");
        __syncthreads();
    }
    asm volatile("cp.async.wait_group 0;" ::: "memory");
    __syncthreads();   // smem about to be reused by epilogue
}

// ------------------------- GEMM1: zv + softmax -> g_O -------------------------
// blockIdx.x = head (0..7) [fast dim -> A-tile L2 reuse], blockIdx.y = m-tile
__global__ __launch_bounds__(256, 2) void gemm1_kernel() {
    extern __shared__ __align__(16) unsigned char sm[];
    const int tid = threadIdx.x;
    float c[4][4][4];

    const __nv_bfloat16* Ag = g_xb  + (size_t)blockIdx.y * 128 * DIM;
    const __nv_bfloat16* Bg = g_W2T + (size_t)blockIdx.x * 128 * DIM;
    run_mainloop(Ag, Bg, smem_u32(sm), tid, c);

    const int l  = tid & 31;
    const int w  = tid >> 5;
    const int wm = w >> 2;
    const int wn = w & 3;
    const int head = blockIdx.x;

    float* Psm = (float*)sm;               // [128][68] exp values
    float* Zs  = (float*)(sm + 34816);     // [2][128] per-row partial sums

    if (wn < 2) {
        float bz2[4][2];
#pragma unroll
        for (int mn = 0; mn < 4; ++mn) {
            int cb = head * 64 + wn * 32 + mn * 8 + 2 * (l & 3);
            bz2[mn][0] = g_bz[cb];
            bz2[mn][1] = g_bz[cb + 1];
        }
#pragma unroll
        for (int mm = 0; mm < 4; ++mm)
#pragma unroll
            for (int rh = 0; rh < 2; ++rh) {
                int r = wm * 64 + mm * 16 + rh * 8 + (l >> 2);
                float part = 0.f;
#pragma unroll
                for (int mn = 0; mn < 4; ++mn) {
                    int cb = wn * 32 + mn * 8 + 2 * (l & 3);
                    float e0 = __expf(c[mm][mn][rh * 2 + 0] + bz2[mn][0]);
                    float e1 = __expf(c[mm][mn][rh * 2 + 1] + bz2[mn][1]);
                    part += e0 + e1;
                    *(float2*)(Psm + r * 68 + cb) = make_float2(e0, e1);
                }
                part += __shfl_xor_sync(0xffffffffu, part, 1);
                part += __shfl_xor_sync(0xffffffffu, part, 2);
                if ((l & 3) == 0) Zs[wn * 128 + r] = part;
            }
    }
    __syncthreads();
    if (wn >= 2) {
        float bv2[4][2];
#pragma unroll
        for (int mn = 0; mn < 4; ++mn) {
            int cb = head * 64 + (wn - 2) * 32 + mn * 8 + 2 * (l & 3);
            bv2[mn][0] = g_bv[cb];
            bv2[mn][1] = g_bv[cb + 1];
        }
#pragma unroll
        for (int mm = 0; mm < 4; ++mm)
#pragma unroll
            for (int rh = 0; rh < 2; ++rh) {
                int r = wm * 64 + mm * 16 + rh * 8 + (l >> 2);
                float inv = 1.0f / (Zs[r] + Zs[128 + r]);
                size_t grow = (size_t)blockIdx.y * 128 + r;
                __nv_bfloat16* op = g_O + grow * DIM + head * 64;
#pragma unroll
                for (int mn = 0; mn < 4; ++mn) {
                    int vc = (wn - 2) * 32 + mn * 8 + 2 * (l & 3);
                    float p0 = Psm[r * 68 + vc];
                    float p1 = Psm[r * 68 + vc + 1];
                    float o0 = p0 * inv * (c[mm][mn][rh * 2 + 0] + bv2[mn][0]);
                    float o1 = p1 * inv * (c[mm][mn][rh * 2 + 1] + bv2[mn][1]);
                    *(__nv_bfloat162*)(op + vc) = __floats2bfloat162_rn(o0, o1);
                }
            }
    }
}

// ------------------------- GEMM2: y = O @ Wp + bp + x -------------------------
// blockIdx.x = n-tile (0..3), blockIdx.y = m-tile
__global__ __launch_bounds__(256, 2) void gemm2_kernel(const float* __restrict__ x,
                                                       const float* __restrict__ bp,
                                                       float* __restrict__ y) {
    extern __shared__ __align__(16) unsigned char sm[];
    const int tid = threadIdx.x;
    float c[4][4][4];

    const __nv_bfloat16* Ag = g_O   + (size_t)blockIdx.y * 128 * DIM;
    const __nv_bfloat16* Bg = g_WpT + (size_t)blockIdx.x * 128 * DIM;
    run_mainloop(Ag, Bg, smem_u32(sm), tid, c);

    const int l  = tid & 31;
    const int w  = tid >> 5;
    const int wm = w >> 2;
    const int wn = w & 3;
    const int cb0 = blockIdx.x * 128 + wn * 32;

    float2 bp2[4];
#pragma unroll
    for (int mn = 0; mn < 4; ++mn)
        bp2[mn] = *(const float2*)(bp + cb0 + mn * 8 + 2 * (l & 3));

#pragma unroll
    for (int mm = 0; mm < 4; ++mm)
#pragma unroll
        for (int rh = 0; rh < 2; ++rh) {
            int r = wm * 64 + mm * 16 + rh * 8 + (l >> 2);
            size_t grow = (size_t)blockIdx.y * 128 + r;
#pragma unroll
            for (int mn = 0; mn < 4; ++mn) {
                int col = cb0 + mn * 8 + 2 * (l & 3);
                float2 xv = *(const float2*)(x + grow * DIM + col);
                float2 o;
                o.x = c[mm][mn][rh * 2 + 0] + bp2[mn].x + xv.x;
                o.y = c[mm][mn][rh * 2 + 1] + bp2[mn].y + xv.y;
                *(float2*)(y + grow * DIM + col) = o;
            }
        }
}

// ------------------------- launch -------------------------
extern "C" void kernel_launch(void* const* d_in, const int* in_sizes, int n_in,
                              void* d_out, int out_size)
{
    const float* x    = (const float*)d_in[0];
    const float* Wqkv = (const float*)d_in[1];
    const float* bqkv = (const float*)d_in[2];
    const float* Wp   = (const float*)d_in[3];
    const float* bp   = (const float*)d_in[4];
    float* y = (float*)d_out;
    (void)in_sizes; (void)n_in; (void)out_size;

    cudaFuncSetAttribute(gemm1_kernel, cudaFuncAttributeMaxDynamicSharedMemorySize, SMEM_BYTES);
    cudaFuncSetAttribute(gemm2_kernel, cudaFuncAttributeMaxDynamicSharedMemorySize, SMEM_BYTES);

    prep_xb <<<(T_TOK * DIM / 4) / 256, 256>>>(x);
    prep_w2t<<<(1024 * DIM) / 256, 256>>>(Wqkv, bqkv);
    prep_wpt<<<(DIM * DIM) / 256, 256>>>(Wp);

    dim3 g1(8, T_TOK / 128);    // head fast, m-tile slow
    gemm1_kernel<<<g1, 256, SMEM_BYTES>>>();

    dim3 g2(4, T_TOK / 128);
    gemm2_kernel<<<g2, 256, SMEM_BYTES>>>(x, bp, y);
}

// round 9
// speedup vs baseline: 5.3961x; 1.0065x over previous
#include <cuda_runtime.h>
#include <cuda_bf16.h>
#include <cuda_fp8.h>
#include <math.h>
#include <stdint.h>

#define T_TOK   32768
#define DIM     512
#define SCALE_F 0.125f

// per-tensor fp8 scales (power of two, exactly invertible)
#define SWZ 256.0f     // (Wq-Wk)*0.125 scaled by 2^8
#define SWV 64.0f      // Wv scaled by 2^6
#define SO  128.0f     // O scaled by 2^7
#define SWP 64.0f      // Wp scaled by 2^6
#define INV_Z  (1.0f / SWZ)
#define INV_V  (1.0f / SWV)
#define INV_P  (1.0f / (SO * SWP))

// smem tile: rows of 64 fp8 (64B) padded to 80B pitch (conflict-free ldmatrix)
#define PITCHB  80
#define ATILE   (128 * PITCHB)            // 10240 B
#define STAGE   (2 * ATILE)               // 20480 B
#define NSTG    4
#define NKT     8                          // 512 / 64
#define SMEM_BYTES (NSTG * STAGE)         // 81920 B/CTA, 2 CTAs/SM

// ------------------------- device scratch (fp8 operands) -------------------------
__device__ uint8_t g_xq [(size_t)T_TOK * DIM];   // x in e4m3
__device__ uint8_t g_Oq [(size_t)T_TOK * DIM];   // (softmax*v)*SO in e4m3
__device__ uint8_t g_W2q[1024 * DIM];            // [n][k], n = h*128 + (z|v), scaled
__device__ uint8_t g_Wpq[DIM * DIM];             // Wp^T scaled
__device__ float g_bz[DIM];
__device__ float g_bv[DIM];

// ------------------------- helpers -------------------------
__device__ __forceinline__ uint32_t smem_u32(const void* p) {
    uint32_t a;
    asm("{ .reg .u64 t; cvta.to.shared.u64 t, %1; cvt.u32.u64 %0, t; }" : "=r"(a) : "l"(p));
    return a;
}
__device__ __forceinline__ void cp16(uint32_t sa, const void* gp) {
    asm volatile("cp.async.cg.shared.global [%0], [%1], 16;" :: "r"(sa), "l"(gp));
}
__device__ __forceinline__ void ld4(uint32_t r[4], uint32_t addr) {
    asm volatile("ldmatrix.sync.aligned.m8n8.x4.shared.b16 {%0,%1,%2,%3}, [%4];"
                 : "=r"(r[0]), "=r"(r[1]), "=r"(r[2]), "=r"(r[3]) : "r"(addr));
}
__device__ __forceinline__ void mma_fp8(float c[4], const uint32_t a[4],
                                        uint32_t b0, uint32_t b1) {
    asm volatile("mma.sync.aligned.m16n8k32.row.col.f32.e4m3.e4m3.f32 "
                 "{%0,%1,%2,%3}, {%4,%5,%6,%7}, {%8,%9}, {%0,%1,%2,%3};"
                 : "+f"(c[0]), "+f"(c[1]), "+f"(c[2]), "+f"(c[3])
                 : "r"(a[0]), "r"(a[1]), "r"(a[2]), "r"(a[3]), "r"(b0), "r"(b1));
}
__device__ __forceinline__ uint16_t fp8x2(float a, float b) {
    return (uint16_t)__nv_cvt_float2_to_fp8x2(make_float2(a, b), __NV_SATFINITE, __NV_E4M3);
}
__device__ __forceinline__ uint8_t fp8s(float a) {
    return (uint8_t)__nv_cvt_float_to_fp8(a, __NV_SATFINITE, __NV_E4M3);
}

// ------------------------- prep kernels -------------------------
__global__ void prep_xq(const float* __restrict__ x) {
    size_t i = (size_t)blockIdx.x * blockDim.x + threadIdx.x;   // 4 floats each
    float4 v = *(const float4*)(x + i * 4);
    uint32_t p = (uint32_t)fp8x2(v.x, v.y) | ((uint32_t)fp8x2(v.z, v.w) << 16);
    *(uint32_t*)(g_xq + i * 4) = p;
}
__global__ void prep_w2q(const float* __restrict__ Wqkv, const float* __restrict__ bqkv) {
    int i = blockIdx.x * blockDim.x + threadIdx.x;   // 0..1024*512-1
    int n = i >> 9, k = i & 511;
    int h = n >> 7, r = n & 127;
    float v;
    if (r < 64) {
        int c = h * 64 + r;
        v = (Wqkv[k * 1536 + c] - Wqkv[k * 1536 + 512 + c]) * (SCALE_F * SWZ);
    } else {
        int c = h * 64 + (r - 64);
        v = Wqkv[k * 1536 + 1024 + c] * SWV;
    }
    g_W2q[n * 512 + k] = fp8s(v);
    if (i < 512) {
        g_bz[i] = (bqkv[i] - bqkv[512 + i]) * SCALE_F;
        g_bv[i] = bqkv[1024 + i];
    }
}
__global__ void prep_wpq(const float* __restrict__ Wp) {
    int i = blockIdx.x * blockDim.x + threadIdx.x;
    int n = i >> 9, k = i & 511;
    g_Wpq[n * 512 + k] = fp8s(Wp[k * 512 + n] * SWP);
}

// ------------------------- mainloop (128x128 tile, fp8, 8 kt, 4-stage) ------------
__device__ __forceinline__ void load_stage(const uint8_t* __restrict__ Ag,
                                           const uint8_t* __restrict__ Bg,
                                           uint32_t stg, int kt, int tid) {
    if (kt < NKT) {
#pragma unroll
        for (int it = 0; it < 2; ++it) {
            int idx = it * 256 + tid;
            int row = idx >> 2, ch = idx & 3;
            uint32_t so = (uint32_t)(row * PITCHB + ch * 16);
            size_t go = (size_t)row * DIM + kt * 64 + ch * 16;
            cp16(stg + so, Ag + go);
            cp16(stg + ATILE + so, Bg + go);
        }
    }
    asm volatile("cp.async.commit_group;" ::: "memory");
}

__device__ __forceinline__ void ld_frags(uint32_t stg, int ks, uint32_t aOff, uint32_t bOff,
                                         uint32_t a[4][4], uint32_t b[2][4]) {
#pragma unroll
    for (int mm = 0; mm < 4; ++mm) ld4(a[mm], stg + aOff + mm * 16 * PITCHB + ks * 32);
#pragma unroll
    for (int pr = 0; pr < 2; ++pr) ld4(b[pr], stg + bOff + pr * 16 * PITCHB + ks * 32);
}

__device__ __forceinline__ void mma_all(float c[4][4][4], uint32_t a[4][4], uint32_t b[2][4]) {
#pragma unroll
    for (int mm = 0; mm < 4; ++mm)
#pragma unroll
        for (int mn = 0; mn < 4; ++mn)
            mma_fp8(c[mm][mn], a[mm], b[mn >> 1][(mn & 1) * 2], b[mn >> 1][(mn & 1) * 2 + 1]);
}

__device__ __forceinline__ void run_mainloop(const uint8_t* __restrict__ Ag,
                                             const uint8_t* __restrict__ Bg,
                                             uint32_t sbase, int tid,
                                             float c[4][4][4]) {
#pragma unroll
    for (int i = 0; i < 4; ++i)
#pragma unroll
        for (int j = 0; j < 4; ++j)
#pragma unroll
            for (int q = 0; q < 4; ++q) c[i][j][q] = 0.f;

    const int l  = tid & 31;
    const int w  = tid >> 5;
    const int wm = w >> 2;
    const int wn = w & 3;
    const uint32_t aOff = (uint32_t)((wm * 64 + (l & 15)) * PITCHB + (l >> 4) * 16);
    const uint32_t bOff = (uint32_t)(ATILE + (wn * 32 + (l & 7) + ((l >> 4) & 1) * 8) * PITCHB
                                     + ((l >> 3) & 1) * 16);

    load_stage(Ag, Bg, sbase + 0 * STAGE, 0, tid);
    load_stage(Ag, Bg, sbase + 1 * STAGE, 1, tid);
    load_stage(Ag, Bg, sbase + 2 * STAGE, 2, tid);
    asm volatile("cp.async.wait_group 1;" ::: "memory");   // stages 0,1 ready
    __syncthreads();

    uint32_t A0[4][4], B0[2][4], A1[4][4], B1[2][4];
    ld_frags(sbase, 0, aOff, bOff, A0, B0);

    for (int kt = 0; kt < NKT; ++kt) {
        load_stage(Ag, Bg, sbase + ((kt + 3) & 3) * STAGE, kt + 3, tid);
        ld_frags(sbase + (kt & 3) * STAGE, 1, aOff, bOff, A1, B1);
        mma_all(c, A0, B0);
        ld_frags(sbase + ((kt + 1) & 3) * STAGE, 0, aOff, bOff, A0, B0);
        mma_all(c, A1, B1);
        asm volatile("cp.async.wait_group 1;" ::: "memory");
        __syncthreads();
    }
    asm volatile("cp.async.wait_group 0;" ::: "memory");
    __syncthreads();   // smem reused by epilogue
}

// ------------------------- GEMM1: zv + softmax -> g_Oq -------------------------
// blockIdx.x = head (fast dim, A-tile L2 reuse), blockIdx.y = m-tile
__global__ __launch_bounds__(256, 2) void gemm1_kernel() {
    extern __shared__ __align__(16) unsigned char sm[];
    const int tid = threadIdx.x;
    float c[4][4][4];

    const uint8_t* Ag = g_xq  + (size_t)blockIdx.y * 128 * DIM;
    const uint8_t* Bg = g_W2q + (size_t)blockIdx.x * 128 * DIM;
    run_mainloop(Ag, Bg, smem_u32(sm), tid, c);

    const int l  = tid & 31;
    const int w  = tid >> 5;
    const int wm = w >> 2;
    const int wn = w & 3;
    const int head = blockIdx.x;

    float* Psm = (float*)sm;               // [128][68] exp values
    float* Zs  = (float*)(sm + 34816);     // [2][128] partial sums

    if (wn < 2) {
        float bz2[4][2];
#pragma unroll
        for (int mn = 0; mn < 4; ++mn) {
            int cb = head * 64 + wn * 32 + mn * 8 + 2 * (l & 3);
            bz2[mn][0] = g_bz[cb];
            bz2[mn][1] = g_bz[cb + 1];
        }
#pragma unroll
        for (int mm = 0; mm < 4; ++mm)
#pragma unroll
            for (int rh = 0; rh < 2; ++rh) {
                int r = wm * 64 + mm * 16 + rh * 8 + (l >> 2);
                float part = 0.f;
#pragma unroll
                for (int mn = 0; mn < 4; ++mn) {
                    int cb = wn * 32 + mn * 8 + 2 * (l & 3);
                    float e0 = __expf(c[mm][mn][rh * 2 + 0] * INV_Z + bz2[mn][0]);
                    float e1 = __expf(c[mm][mn][rh * 2 + 1] * INV_Z + bz2[mn][1]);
                    part += e0 + e1;
                    *(float2*)(Psm + r * 68 + cb) = make_float2(e0, e1);
                }
                part += __shfl_xor_sync(0xffffffffu, part, 1);
                part += __shfl_xor_sync(0xffffffffu, part, 2);
                if ((l & 3) == 0) Zs[wn * 128 + r] = part;
            }
    }
    __syncthreads();
    if (wn >= 2) {
        float bv2[4][2];
#pragma unroll
        for (int mn = 0; mn < 4; ++mn) {
            int cb = head * 64 + (wn - 2) * 32 + mn * 8 + 2 * (l & 3);
            bv2[mn][0] = g_bv[cb];
            bv2[mn][1] = g_bv[cb + 1];
        }
#pragma unroll
        for (int mm = 0; mm < 4; ++mm)
#pragma unroll
            for (int rh = 0; rh < 2; ++rh) {
                int r = wm * 64 + mm * 16 + rh * 8 + (l >> 2);
                float inv = SO / (Zs[r] + Zs[128 + r]);
                size_t grow = (size_t)blockIdx.y * 128 + r;
                uint8_t* op = g_Oq + grow * DIM + head * 64;
#pragma unroll
                for (int mn = 0; mn < 4; ++mn) {
                    int vc = (wn - 2) * 32 + mn * 8 + 2 * (l & 3);
                    float p0 = Psm[r * 68 + vc];
                    float p1 = Psm[r * 68 + vc + 1];
                    float o0 = p0 * inv * (c[mm][mn][rh * 2 + 0] * INV_V + bv2[mn][0]);
                    float o1 = p1 * inv * (c[mm][mn][rh * 2 + 1] * INV_V + bv2[mn][1]);
                    *(uint16_t*)(op + vc) = fp8x2(o0, o1);
                }
            }
    }
}

// ------------------------- GEMM2: y = O @ Wp + bp + x -------------------------
__global__ __launch_bounds__(256, 2) void gemm2_kernel(const float* __restrict__ x,
                                                       const float* __restrict__ bp,
                                                       float* __restrict__ y) {
    extern __shared__ __align__(16) unsigned char sm[];
    const int tid = threadIdx.x;
    float c[4][4][4];

    const uint8_t* Ag = g_Oq  + (size_t)blockIdx.y * 128 * DIM;
    const uint8_t* Bg = g_Wpq + (size_t)blockIdx.x * 128 * DIM;
    run_mainloop(Ag, Bg, smem_u32(sm), tid, c);

    const int l  = tid & 31;
    const int w  = tid >> 5;
    const int wm = w >> 2;
    const int wn = w & 3;
    const int cb0 = blockIdx.x * 128 + wn * 32;

    float2 bp2[4];
#pragma unroll
    for (int mn = 0; mn < 4; ++mn)
        bp2[mn] = *(const float2*)(bp + cb0 + mn * 8 + 2 * (l & 3));

#pragma unroll
    for (int mm = 0; mm < 4; ++mm)
#pragma unroll
        for (int rh = 0; rh < 2; ++rh) {
            int r = wm * 64 + mm * 16 + rh * 8 + (l >> 2);
            size_t grow = (size_t)blockIdx.y * 128 + r;
#pragma unroll
            for (int mn = 0; mn < 4; ++mn) {
                int col = cb0 + mn * 8 + 2 * (l & 3);
                float2 xv = *(const float2*)(x + grow * DIM + col);
                float2 o;
                o.x = c[mm][mn][rh * 2 + 0] * INV_P + bp2[mn].x + xv.x;
                o.y = c[mm][mn][rh * 2 + 1] * INV_P + bp2[mn].y + xv.y;
                *(float2*)(y + grow * DIM + col) = o;
            }
        }
}

// ------------------------- launch -------------------------
extern "C" void kernel_launch(void* const* d_in, const int* in_sizes, int n_in,
                              void* d_out, int out_size)
{
    const float* x    = (const float*)d_in[0];
    const float* Wqkv = (const float*)d_in[1];
    const float* bqkv = (const float*)d_in[2];
    const float* Wp   = (const float*)d_in[3];
    const float* bp   = (const float*)d_in[4];
    float* y = (float*)d_out;
    (void)in_sizes; (void)n_in; (void)out_size;

    cudaFuncSetAttribute(gemm1_kernel, cudaFuncAttributeMaxDynamicSharedMemorySize, SMEM_BYTES);
    cudaFuncSetAttribute(gemm2_kernel, cudaFuncAttributeMaxDynamicSharedMemorySize, SMEM_BYTES);

    prep_xq <<<(T_TOK * DIM / 4) / 256, 256>>>(x);
    prep_w2q<<<(1024 * DIM) / 256, 256>>>(Wqkv, bqkv);
    prep_wpq<<<(DIM * DIM) / 256, 256>>>(Wp);

    dim3 g1(8, T_TOK / 128);
    gemm1_kernel<<<g1, 256, SMEM_BYTES>>>();

    dim3 g2(4, T_TOK / 128);
    gemm2_kernel<<<g2, 256, SMEM_BYTES>>>(x, bp, y);
}